// round 11
// baseline (speedup 1.0000x reference)
#include <cuda_runtime.h>

// Problem constants (fixed shapes for this problem)
#define BXN 128     // batch of X paths (i)
#define BYN 128     // batch of Y paths (j)
#define TN  1024    // time points
#define DN  64      // path dimension
#define NSTEPS 1023 // TN-1
#define CL  16      // outputs (t values) per chunk
#define NC  64      // chunks (CL*NC == TN)
#define TI  64      // CTA tile in i
#define TJ  64      // CTA tile in j
#define NTHREADS 128
#define PAD 68      // padded smem row (floats), 16B-aligned

// Scratch (no allocation allowed -> device globals)
__device__ float g_Cprod[NC * BXN * BYN];  // per-chunk total product
__device__ float g_Pexc [NC * BXN * BYN];  // exclusive prefix product

// ---------------------------------------------------------------------------
// K1: per-chunk local cumulative products.
// Grid (4, NC). CTA = 128 threads (warps 0-3 -> all 4 SMSPs). 64x64 (i,j)
// tile, 8x4 per-thread sub-tile: per warp-d 3 LDS.128 (12 crossbar cyc) vs
// 32 FFMA (16 fma cyc on 2 warps/SMSP) -> fma-pipe bound.
// NO register-resident path rows (that spilled at 255 regs in R5/R6): each
// step loads rows s+1 (L1-hot) and s+2 from gmem during the FMA phase and
// keeps only the 16-float4 increment in registers until the STS phase.
// Output staged 4 t's at a time, flushed as contiguous float4 runs.
// ---------------------------------------------------------------------------
__launch_bounds__(NTHREADS)
__global__ void k1_chunk(const float* __restrict__ X,
                         const float* __restrict__ Y,
                         float* __restrict__ out)
{
    const int i0    = (blockIdx.x & 1) * TI;
    const int j0    = (blockIdx.x >> 1) * TJ;
    const int c     = blockIdx.y;
    const int tbase = c * CL;

    __shared__ float dxs[DN][PAD];       // [d][i] increments
    __shared__ float dys[DN][PAD];       // [d][j] increments
    __shared__ float staging[4][TI*TJ];  // 4 t-slots x 4096 pairs (64KB)

    const int tid = threadIdx.x;
    const int tx  = tid & 15;   // j-group (4 j's)
    const int ty  = tid >> 4;   // i-group (8 i's)

    // loader role: one full 64-float row per thread (no register residency)
    const int  r    = tid & 63;
    const bool isY  = (tid >= 64);
    const float* row = (isY ? (Y + ((size_t)(j0 + r) * TN + tbase) * DN)
                            : (X + ((size_t)(i0 + r) * TN + tbase) * DN));
    float* dst = isY ? &dys[0][0] : &dxs[0][0];   // dst[d*PAD + r]

    const float STEP = 1.0f / 1023.0f;  // matches jnp.linspace delta in fp32

    // ---- prologue: increments for step tbase (rows tbase, tbase+1) ----
#pragma unroll
    for (int q = 0; q < 16; q++) {
        float4 p0 = *(const float4*)(row + q * 4);
        float4 p1 = *(const float4*)(row + DN + q * 4);
        const int d0 = q * 4;
        dst[(d0 + 0) * PAD + r] = p1.x - p0.x;
        dst[(d0 + 1) * PAD + r] = p1.y - p0.y;
        dst[(d0 + 2) * PAD + r] = p1.z - p0.z;
        dst[(d0 + 3) * PAD + r] = p1.w - p0.w;
    }
    __syncthreads();

    float K[8][4];
#pragma unroll
    for (int a = 0; a < 8; a++)
#pragma unroll
        for (int b = 0; b < 4; b++) K[a][b] = 1.0f;

#pragma unroll 1
    for (int k = 0; k < CL; k++) {
        const int s    = tbase + k;
        const int slot = k & 3;
        const bool more = (k + 1 < CL) && (s + 1 < NSTEPS);

        // ---- 1. stage current K (= out[t=s] before cross-chunk prefix) ----
#pragma unroll
        for (int a = 0; a < 8; a++) {
            float4 v = make_float4(K[a][0], K[a][1], K[a][2], K[a][3]);
            *(float4*)&staging[slot][(ty * 8 + a) * TJ + tx * 4] = v;
        }

        // ---- 2. next increment: load rows s+1 (L1 hit) and s+2, keep only
        //         the difference in registers (64 regs, no spill) ----
        float4 diff[16];
        if (more) {
            const float* r1 = row + (size_t)(k + 1) * DN;
#pragma unroll
            for (int q = 0; q < 16; q++) {
                float4 a = *(const float4*)(r1 + q * 4);
                float4 b = *(const float4*)(r1 + DN + q * 4);
                diff[q] = make_float4(b.x - a.x, b.y - a.y, b.z - a.z, b.w - a.w);
            }
        }

        // ---- 3. dot phase + scan update ----
        if (s < NSTEPS) {
            const float t1  = (s + 1 == NSTEPS) ? 1.0f : (float)(s + 1) * STEP;
            const float t0  = (float)s * STEP;
            const float inv = 1.0f / (t1 - t0);

            float acc[8][4];
#pragma unroll
            for (int a = 0; a < 8; a++)
#pragma unroll
                for (int b = 0; b < 4; b++) acc[a][b] = 0.0f;

#pragma unroll 8
            for (int d = 0; d < DN; d++) {
                const float4 yb  = *(const float4*)&dys[d][tx * 4];
                const float4 xa0 = *(const float4*)&dxs[d][ty * 8];
                const float4 xa1 = *(const float4*)&dxs[d][ty * 8 + 4];
                acc[0][0] = fmaf(xa0.x, yb.x, acc[0][0]);
                acc[0][1] = fmaf(xa0.x, yb.y, acc[0][1]);
                acc[0][2] = fmaf(xa0.x, yb.z, acc[0][2]);
                acc[0][3] = fmaf(xa0.x, yb.w, acc[0][3]);
                acc[1][0] = fmaf(xa0.y, yb.x, acc[1][0]);
                acc[1][1] = fmaf(xa0.y, yb.y, acc[1][1]);
                acc[1][2] = fmaf(xa0.y, yb.z, acc[1][2]);
                acc[1][3] = fmaf(xa0.y, yb.w, acc[1][3]);
                acc[2][0] = fmaf(xa0.z, yb.x, acc[2][0]);
                acc[2][1] = fmaf(xa0.z, yb.y, acc[2][1]);
                acc[2][2] = fmaf(xa0.z, yb.z, acc[2][2]);
                acc[2][3] = fmaf(xa0.z, yb.w, acc[2][3]);
                acc[3][0] = fmaf(xa0.w, yb.x, acc[3][0]);
                acc[3][1] = fmaf(xa0.w, yb.y, acc[3][1]);
                acc[3][2] = fmaf(xa0.w, yb.z, acc[3][2]);
                acc[3][3] = fmaf(xa0.w, yb.w, acc[3][3]);
                acc[4][0] = fmaf(xa1.x, yb.x, acc[4][0]);
                acc[4][1] = fmaf(xa1.x, yb.y, acc[4][1]);
                acc[4][2] = fmaf(xa1.x, yb.z, acc[4][2]);
                acc[4][3] = fmaf(xa1.x, yb.w, acc[4][3]);
                acc[5][0] = fmaf(xa1.y, yb.x, acc[5][0]);
                acc[5][1] = fmaf(xa1.y, yb.y, acc[5][1]);
                acc[5][2] = fmaf(xa1.y, yb.z, acc[5][2]);
                acc[5][3] = fmaf(xa1.y, yb.w, acc[5][3]);
                acc[6][0] = fmaf(xa1.z, yb.x, acc[6][0]);
                acc[6][1] = fmaf(xa1.z, yb.y, acc[6][1]);
                acc[6][2] = fmaf(xa1.z, yb.z, acc[6][2]);
                acc[6][3] = fmaf(xa1.z, yb.w, acc[6][3]);
                acc[7][0] = fmaf(xa1.w, yb.x, acc[7][0]);
                acc[7][1] = fmaf(xa1.w, yb.y, acc[7][1]);
                acc[7][2] = fmaf(xa1.w, yb.z, acc[7][2]);
                acc[7][3] = fmaf(xa1.w, yb.w, acc[7][3]);
            }

#pragma unroll
            for (int a = 0; a < 8; a++)
#pragma unroll
                for (int b = 0; b < 4; b++)
                    K[a][b] *= fmaf(acc[a][b], inv, 1.0f);
        }

        // ---- 4. barrier: increment readers + staging writers retired ----
        __syncthreads();

        // ---- 5. flush 4 staged t-slices as contiguous float4 runs ----
        if (slot == 3) {
            const int tflush = tbase + k - 3;
#pragma unroll
            for (int w = 0; w < 32; w++) {
                int p  = tid + NTHREADS * w;   // pair index in 64x64 tile
                int pi = p >> 6, pj = p & 63;
                float4 v = make_float4(staging[0][p], staging[1][p],
                                       staging[2][p], staging[3][p]);
                *(float4*)(out + ((size_t)(i0 + pi) * BYN + (j0 + pj)) * TN + tflush) = v;
            }
        }

        // ---- 6. store increments for step k+1 ----
        if (more) {
#pragma unroll
            for (int q = 0; q < 16; q++) {
                const int d0 = q * 4;
                dst[(d0 + 0) * PAD + r] = diff[q].x;
                dst[(d0 + 1) * PAD + r] = diff[q].y;
                dst[(d0 + 2) * PAD + r] = diff[q].z;
                dst[(d0 + 3) * PAD + r] = diff[q].w;
            }
        }

        // ---- 7. barrier: increments visible; staging safe to overwrite ----
        __syncthreads();
    }

    // chunk-total product (for cross-chunk prefix)
    float* Cp = g_Cprod + (size_t)c * (BXN * BYN);
#pragma unroll
    for (int a = 0; a < 8; a++) {
        float4 v = make_float4(K[a][0], K[a][1], K[a][2], K[a][3]);
        *(float4*)&Cp[(i0 + ty * 8 + a) * BYN + (j0 + tx * 4)] = v;
    }
}

// ---------------------------------------------------------------------------
// K2: exclusive prefix product across the NC chunks, per (i,j) pair. Tiny.
// ---------------------------------------------------------------------------
__global__ void k2_prefix()
{
    const int p = blockIdx.x * blockDim.x + threadIdx.x;
    if (p >= BXN * BYN) return;
    float run = 1.0f;
#pragma unroll
    for (int c = 0; c < NC; c++) {
        const float v = g_Cprod[c * BXN * BYN + p];
        g_Pexc[c * BXN * BYN + p] = run;
        run *= v;
    }
}

// ---------------------------------------------------------------------------
// K3: out[i,j,t] *= Pexc[chunk(t), i, j]  (streaming float4 rescale)
// ---------------------------------------------------------------------------
__global__ void k3_scale(float* __restrict__ out)
{
    const size_t v = (size_t)blockIdx.x * blockDim.x + threadIdx.x;
    const size_t e = v * 4;              // element index
    const int pair = (int)(e >> 10);     // / TN
    const int t    = (int)(e & (TN - 1));
    const int c    = t >> 4;             // / CL (CL == 16)
    const float pf = g_Pexc[c * BXN * BYN + pair];
    float4 val = ((float4*)out)[v];
    val.x *= pf; val.y *= pf; val.z *= pf; val.w *= pf;
    ((float4*)out)[v] = val;
}

extern "C" void kernel_launch(void* const* d_in, const int* in_sizes, int n_in,
                              void* d_out, int out_size)
{
    const float* X = (const float*)d_in[0];
    const float* Y = (const float*)d_in[1];
    float* out = (float*)d_out;

    dim3 g1(4, NC);                      // 4 tiles x 64 chunks = 256 CTAs
    k1_chunk<<<g1, NTHREADS>>>(X, Y, out);

    k2_prefix<<<(BXN * BYN + 255) / 256, 256>>>();

    const int nvec = BXN * BYN * TN / 4; // 4M float4
    k3_scale<<<(nvec + 255) / 256, 256>>>(out);
}

// round 12
// speedup vs baseline: 1.3276x; 1.3276x over previous
#include <cuda_runtime.h>
#include <cstdint>

// Problem constants (fixed shapes)
#define BXN 128
#define BYN 128
#define TN  1024
#define DN  64
#define NSTEPS 1023
#define CL  16      // t-steps per chunk
#define NC  64      // chunks
#define TI  64
#define TJ  64
#define NTHREADS 128
#define PAD 68      // smem row stride (floats), keeps float4 alignment + no conflicts

__device__ float g_Cprod[NC * BXN * BYN];
__device__ float g_Pexc [NC * BXN * BYN];

__device__ __forceinline__ void cp_async16(uint32_t dst, const float* src) {
    asm volatile("cp.async.ca.shared.global [%0], [%1], 16;\n" :: "r"(dst), "l"(src));
}
__device__ __forceinline__ void cp_commit() {
    asm volatile("cp.async.commit_group;\n");
}
__device__ __forceinline__ void cp_wait0() {
    asm volatile("cp.async.wait_group 0;\n");
}

// ---------------------------------------------------------------------------
// K1: per-chunk local cumulative products.
// Grid (4, NC), 128 threads (all 4 SMSPs), 64x64 tile, 8x4 micro-tile.
// Row data moves gmem -> smem COALESCED via cp.async (4 wavefronts per warp
// instr instead of 32 for the old per-thread-row LDGs -- this was the
// bottleneck in R1-R11). Thread tid then diffs its own row (rawN[tid]) against
// register cur[16] and writes transposed increments to dxs/dys.
// ---------------------------------------------------------------------------
__launch_bounds__(NTHREADS, 2)
__global__ void k1_chunk(const float* __restrict__ X,
                         const float* __restrict__ Y,
                         float* __restrict__ out)
{
    const int i0    = (blockIdx.x & 1) * TI;
    const int j0    = (blockIdx.x >> 1) * TJ;
    const int tbase = blockIdx.y * CL;

    __shared__ float rawN[128 * PAD];        // raw rows of one time point (34.8KB)
    __shared__ float dxs[DN][PAD];           // transposed increments [d][i]
    __shared__ float dys[DN][PAD];           // [d][j]
    __shared__ float staging[2][TI * TJ];    // 2 t-slots (32KB)

    const int tid  = threadIdx.x;
    const int tx   = tid & 15;               // j-group (4 j's)
    const int ty   = tid >> 4;               // i-group (8 i's)
    const int rh   = tid >> 4;               // loader row-offset within 8-row group
    const int quad = tid & 15;               // d-quad

    const float STEP = 1.0f / 1023.0f;       // jnp.linspace delta in fp32

    // coalesced loader bases: q=0..7 -> X rows i0+q*8+rh ; q=8..15 -> Y rows
    const float* gx = X + (size_t)(i0 + rh) * TN * DN + quad * 4;
    const float* gy = Y + (size_t)(j0 + rh) * TN * DN + quad * 4;
    const size_t RSTRIDE = (size_t)8 * TN * DN;   // 8 rows in elements
    const uint32_t sbase = (uint32_t)__cvta_generic_to_shared(rawN)
                         + (uint32_t)(rh * PAD + quad * 4) * 4u;

    // issue one full time-slice (128 rows x 64 d) coalesced into rawN
    auto load_slice = [&](int tt) {
        const size_t off = (size_t)tt * DN;
#pragma unroll
        for (int q = 0; q < 8; q++)
            cp_async16(sbase + (uint32_t)(q * 8 * PAD * 4), gx + q * RSTRIDE + off);
#pragma unroll
        for (int q = 0; q < 8; q++)
            cp_async16(sbase + (uint32_t)((q + 8) * 8 * PAD * 4), gy + q * RSTRIDE + off);
        cp_commit();
    };

    // transposer destination: thread tid owns raw row tid
    float* dst = (tid < 64) ? &dxs[0][0] : &dys[0][0];
    const int r = tid & 63;

    float4 cur[16];

    // ---- prologue ----
    load_slice(tbase + 1);
    cp_wait0();
    __syncthreads();
#pragma unroll
    for (int q = 0; q < 16; q++)
        cur[q] = *(const float4*)&rawN[tid * PAD + q * 4];
    __syncthreads();

    load_slice(tbase);
    cp_wait0();
    __syncthreads();
#pragma unroll
    for (int q = 0; q < 16; q++) {
        float4 o = *(const float4*)&rawN[tid * PAD + q * 4];
        const int d0 = q * 4;
        dst[(d0 + 0) * PAD + r] = cur[q].x - o.x;
        dst[(d0 + 1) * PAD + r] = cur[q].y - o.y;
        dst[(d0 + 2) * PAD + r] = cur[q].z - o.z;
        dst[(d0 + 3) * PAD + r] = cur[q].w - o.w;
    }
    __syncthreads();

    float K[8][4];
#pragma unroll
    for (int a = 0; a < 8; a++)
#pragma unroll
        for (int b = 0; b < 4; b++) K[a][b] = 1.0f;

#pragma unroll 1
    for (int k = 0; k < CL; k++) {
        const int  s    = tbase + k;
        const bool more = (k + 1 < CL) && (s + 1 < NSTEPS);

        // ---- stage current K (local value of out[t=s]) ----
#pragma unroll
        for (int a = 0; a < 8; a++) {
            float4 v = make_float4(K[a][0], K[a][1], K[a][2], K[a][3]);
            *(float4*)&staging[k & 1][(ty * 8 + a) * TJ + tx * 4] = v;
        }

        // ---- kick off coalesced load of rows(s+2); lands during FMA ----
        if (more) load_slice(s + 2);

        // ---- dot + scan update ----
        if (s < NSTEPS) {
            const float t1  = (s + 1 == NSTEPS) ? 1.0f : (float)(s + 1) * STEP;
            const float t0  = (float)s * STEP;
            const float inv = 1.0f / (t1 - t0);

            float acc[8][4];
#pragma unroll
            for (int a = 0; a < 8; a++)
#pragma unroll
                for (int b = 0; b < 4; b++) acc[a][b] = 0.0f;

#pragma unroll 8
            for (int d = 0; d < DN; d++) {
                const float4 yb  = *(const float4*)&dys[d][tx * 4];
                const float4 xa0 = *(const float4*)&dxs[d][ty * 8];
                const float4 xa1 = *(const float4*)&dxs[d][ty * 8 + 4];
                acc[0][0] = fmaf(xa0.x, yb.x, acc[0][0]);
                acc[0][1] = fmaf(xa0.x, yb.y, acc[0][1]);
                acc[0][2] = fmaf(xa0.x, yb.z, acc[0][2]);
                acc[0][3] = fmaf(xa0.x, yb.w, acc[0][3]);
                acc[1][0] = fmaf(xa0.y, yb.x, acc[1][0]);
                acc[1][1] = fmaf(xa0.y, yb.y, acc[1][1]);
                acc[1][2] = fmaf(xa0.y, yb.z, acc[1][2]);
                acc[1][3] = fmaf(xa0.y, yb.w, acc[1][3]);
                acc[2][0] = fmaf(xa0.z, yb.x, acc[2][0]);
                acc[2][1] = fmaf(xa0.z, yb.y, acc[2][1]);
                acc[2][2] = fmaf(xa0.z, yb.z, acc[2][2]);
                acc[2][3] = fmaf(xa0.z, yb.w, acc[2][3]);
                acc[3][0] = fmaf(xa0.w, yb.x, acc[3][0]);
                acc[3][1] = fmaf(xa0.w, yb.y, acc[3][1]);
                acc[3][2] = fmaf(xa0.w, yb.z, acc[3][2]);
                acc[3][3] = fmaf(xa0.w, yb.w, acc[3][3]);
                acc[4][0] = fmaf(xa1.x, yb.x, acc[4][0]);
                acc[4][1] = fmaf(xa1.x, yb.y, acc[4][1]);
                acc[4][2] = fmaf(xa1.x, yb.z, acc[4][2]);
                acc[4][3] = fmaf(xa1.x, yb.w, acc[4][3]);
                acc[5][0] = fmaf(xa1.y, yb.x, acc[5][0]);
                acc[5][1] = fmaf(xa1.y, yb.y, acc[5][1]);
                acc[5][2] = fmaf(xa1.y, yb.z, acc[5][2]);
                acc[5][3] = fmaf(xa1.y, yb.w, acc[5][3]);
                acc[6][0] = fmaf(xa1.z, yb.x, acc[6][0]);
                acc[6][1] = fmaf(xa1.z, yb.y, acc[6][1]);
                acc[6][2] = fmaf(xa1.z, yb.z, acc[6][2]);
                acc[6][3] = fmaf(xa1.z, yb.w, acc[6][3]);
                acc[7][0] = fmaf(xa1.w, yb.x, acc[7][0]);
                acc[7][1] = fmaf(xa1.w, yb.y, acc[7][1]);
                acc[7][2] = fmaf(xa1.w, yb.z, acc[7][2]);
                acc[7][3] = fmaf(xa1.w, yb.w, acc[7][3]);
            }

#pragma unroll
            for (int a = 0; a < 8; a++)
#pragma unroll
                for (int b = 0; b < 4; b++)
                    K[a][b] *= fmaf(acc[a][b], inv, 1.0f);
        }

        if (more) cp_wait0();   // own copies landed; barrier publishes all
        __syncthreads();        // b1: dxs readers done; staging + rawN visible

        // ---- flush 2 staged t-slices as contiguous float2 runs ----
        if (k & 1) {
            const int tflush = s - 1;
#pragma unroll
            for (int w = 0; w < 32; w++) {
                int p  = tid + NTHREADS * w;
                int pi = p >> 6, pj = p & 63;
                float2 v = make_float2(staging[0][p], staging[1][p]);
                *(float2*)(out + ((size_t)(i0 + pi) * BYN + (j0 + pj)) * TN + tflush) = v;
            }
        }

        // ---- diff + transpose for step k+1 (reads rawN = rows s+2) ----
        if (more) {
#pragma unroll
            for (int q = 0; q < 16; q++) {
                float4 n = *(const float4*)&rawN[tid * PAD + q * 4];
                const int d0 = q * 4;
                dst[(d0 + 0) * PAD + r] = n.x - cur[q].x;
                dst[(d0 + 1) * PAD + r] = n.y - cur[q].y;
                dst[(d0 + 2) * PAD + r] = n.z - cur[q].z;
                dst[(d0 + 3) * PAD + r] = n.w - cur[q].w;
                cur[q] = n;
            }
        }
        __syncthreads();        // b2: dxs ready; rawN free for next cp.async
    }

    // chunk-total product
    float* Cp = g_Cprod + (size_t)blockIdx.y * (BXN * BYN);
#pragma unroll
    for (int a = 0; a < 8; a++) {
        float4 v = make_float4(K[a][0], K[a][1], K[a][2], K[a][3]);
        *(float4*)&Cp[(i0 + ty * 8 + a) * BYN + (j0 + tx * 4)] = v;
    }
}

// ---------------------------------------------------------------------------
__global__ void k2_prefix()
{
    const int p = blockIdx.x * blockDim.x + threadIdx.x;
    if (p >= BXN * BYN) return;
    float run = 1.0f;
#pragma unroll
    for (int c = 0; c < NC; c++) {
        const float v = g_Cprod[c * BXN * BYN + p];
        g_Pexc[c * BXN * BYN + p] = run;
        run *= v;
    }
}

// ---------------------------------------------------------------------------
__global__ void k3_scale(float* __restrict__ out)
{
    const size_t v = (size_t)blockIdx.x * blockDim.x + threadIdx.x;
    const size_t e = v * 4;
    const int pair = (int)(e >> 10);
    const int t    = (int)(e & (TN - 1));
    const int c    = t >> 4;             // CL == 16
    const float pf = g_Pexc[c * BXN * BYN + pair];
    float4 val = ((float4*)out)[v];
    val.x *= pf; val.y *= pf; val.z *= pf; val.w *= pf;
    ((float4*)out)[v] = val;
}

extern "C" void kernel_launch(void* const* d_in, const int* in_sizes, int n_in,
                              void* d_out, int out_size)
{
    const float* X = (const float*)d_in[0];
    const float* Y = (const float*)d_in[1];
    float* out = (float*)d_out;

    dim3 g1(4, NC);                      // 256 CTAs
    k1_chunk<<<g1, NTHREADS>>>(X, Y, out);

    k2_prefix<<<(BXN * BYN + 255) / 256, 256>>>();

    const int nvec = BXN * BYN * TN / 4;
    k3_scale<<<(nvec + 255) / 256, 256>>>(out);
}